// round 6
// baseline (speedup 1.0000x reference)
#include <cuda_runtime.h>
#include <cstdint>

constexpr int Bc=4, Nn=2048, Dd=256, Hh=4;
constexpr int TI=32, TJ=32, NT=Nn/TJ;   // 64 tiles

__device__ float g_WhT [Bc*Dd*Nn];      // [b][c][j]
__device__ float g_esrc[Bc*Hh*Nn];
__device__ float g_edst[Bc*Hh*Nn];

__device__ __forceinline__ float totf(float x){
    uint32_t u; asm("cvt.rna.tf32.f32 %0, %1;" : "=r"(u) : "f"(x));
    return __uint_as_float(u);
}
__device__ __forceinline__ void mma8(float* d, float4 a, float2 b){
    asm volatile("mma.sync.aligned.m16n8k8.row.col.f32.tf32.tf32.f32 "
        "{%0,%1,%2,%3}, {%4,%5,%6,%7}, {%8,%9}, {%0,%1,%2,%3};"
        : "+f"(d[0]), "+f"(d[1]), "+f"(d[2]), "+f"(d[3])
        : "r"(__float_as_uint(a.x)), "r"(__float_as_uint(a.y)),
          "r"(__float_as_uint(a.z)), "r"(__float_as_uint(a.w)),
          "r"(__float_as_uint(b.x)), "r"(__float_as_uint(b.y)));
}

// ---------------------------------------------------------------------------
// K1: Wh = h @ W, stored transposed into g_WhT[b][c][j]
// ---------------------------------------------------------------------------
__global__ __launch_bounds__(256)
void gemm_h_w(const float* __restrict__ A, const float* __restrict__ Bw){
    __shared__ float As[16][64];
    __shared__ float Bs[16][64];
    __shared__ float Tr[64][65];
    const int tid=threadIdx.x;
    const int m0=blockIdx.x*64, n0=blockIdx.y*64;
    const int tm=tid>>4, tn=tid&15;
    const int lm=tid>>2, lk=(tid&3)*4;
    const int lbk=tid>>4, lbn=(tid&15)*4;
    float acc[4][4];
#pragma unroll
    for(int r=0;r<4;r++)
#pragma unroll
        for(int c=0;c<4;c++) acc[r][c]=0.f;
    for(int k0=0;k0<256;k0+=16){
        float4 av = *(const float4*)(A + (size_t)(m0+lm)*256 + k0+lk);
        As[lk+0][lm]=av.x; As[lk+1][lm]=av.y; As[lk+2][lm]=av.z; As[lk+3][lm]=av.w;
        *(float4*)&Bs[lbk][lbn] = *(const float4*)(Bw + (size_t)(k0+lbk)*256 + n0+lbn);
        __syncthreads();
#pragma unroll
        for(int k=0;k<16;k++){
            float4 a4=*(const float4*)&As[k][tm*4];
            float4 b4=*(const float4*)&Bs[k][tn*4];
            float ar[4]={a4.x,a4.y,a4.z,a4.w}, br[4]={b4.x,b4.y,b4.z,b4.w};
#pragma unroll
            for(int r=0;r<4;r++)
#pragma unroll
                for(int c=0;c<4;c++) acc[r][c]+=ar[r]*br[c];
        }
        __syncthreads();
    }
#pragma unroll
    for(int r=0;r<4;r++)
#pragma unroll
        for(int c=0;c<4;c++) Tr[tn*4+c][tm*4+r]=acc[r][c];
    __syncthreads();
    const int b = m0>>11, ml = m0&2047;
    const int n = tid>>2, ms = (tid&3)*16;
    float* dst = g_WhT + ((size_t)(b*Dd + n0 + n))*Nn + ml + ms;
#pragma unroll
    for(int k=0;k<4;k++)
        *(float4*)(dst + k*4) = make_float4(Tr[n][ms+k*4], Tr[n][ms+k*4+1],
                                            Tr[n][ms+k*4+2], Tr[n][ms+k*4+3]);
}

// ---------------------------------------------------------------------------
// K2: e_src/e_dst from WhT (coalesced over n)
// ---------------------------------------------------------------------------
__global__ __launch_bounds__(128)
void gat_attn_proj(const float* __restrict__ a_src, const float* __restrict__ a_dst){
    __shared__ float sa[64], sd[64];
    const int tid=threadIdx.x;
    const int chunk=blockIdx.x&15, h=(blockIdx.x>>4)&3, b=blockIdx.x>>6;
    if(tid<64){ sa[tid]=a_src[h*64+tid]; sd[tid]=a_dst[h*64+tid]; }
    __syncthreads();
    const int n = chunk*128 + tid;
    const float* wp = g_WhT + ((size_t)(b*Dd + h*64))*Nn + n;
    float ss=0.f, ds=0.f;
#pragma unroll 8
    for(int d=0; d<64; d++){
        float w = wp[(size_t)d*Nn];
        ss += w*sa[d]; ds += w*sd[d];
    }
    int g = (b*Hh+h)*Nn + n;
    g_esrc[g]=ss; g_edst[g]=ds;
}

// ---------------------------------------------------------------------------
// K3 (main): fused stats + alpha + HMMA tf32.
// Block: 256 thr, TI=32 rows, full j-range. 2 CTAs/SM.
// Pass 1: adj -> nibble bitmask (smem, 16KB) + row sums (no max-sub).
// Pass 2: per TJ=32 tile: alpha (from bits) -> A frags + gmem;
//         WhT reg-prefetch -> B frags; 32 HMMA/warp.
// ---------------------------------------------------------------------------
constexpr int OFF_B    = 16384;           // A frags [0,16384)
constexpr int OFF_BITS = OFF_B + 128*33*8;     // 50176
constexpr int OFF_ES   = OFF_BITS + 16384;     // 66560
constexpr int OFF_IV   = OFF_ES + 512;         // 67072
constexpr int SMEM_MAIN= OFF_IV + 512;         // 67584

__global__ __launch_bounds__(256, 2)
void gat_main(const int* __restrict__ adj, float* __restrict__ h_out,
              float* __restrict__ alpha_out, int write_alpha)
{
    extern __shared__ char smem[];
    float4*  As    = (float4*)smem;
    float2*  Bs2   = (float2*)(smem + OFF_B);
    uint8_t* bitsb = (uint8_t*)(smem + OFF_BITS);
    float*   es    = (float*)(smem + OFF_ES);   // [4][32]
    float*   iv    = (float*)(smem + OFF_IV);   // [4][32]

    const int tid  = threadIdx.x;
    const int lane = tid & 31;
    const int b  = blockIdx.x >> 6;
    const int i0 = (blockIdx.x & 63) * TI;

    if(tid < 128)
        es[tid] = g_esrc[(b*Hh + (tid>>5))*Nn + i0 + (tid&31)];
    __syncthreads();

    // ================= pass 1: bitmask + row sums =================
    {
        const int i = tid>>3, g = tid&7;
        const int*   arow = adj + ((size_t)(b*Nn + i0 + i))*Nn + g*4;
        const float* edb  = g_edst + (size_t)(b*Hh)*Nn + g*4;
        float E[4] = {es[i], es[32+i], es[64+i], es[96+i]};
        float S[4] = {0.f,0.f,0.f,0.f};
        for(int q=0;q<64;q++){
            int4 a = *(const int4*)(arow + q*32);
            float4 dv[4];
#pragma unroll
            for(int h=0;h<4;h++)
                dv[h] = *(const float4*)(edb + (size_t)h*Nn + q*32);
            int m[4] = {a.x, a.y, a.z, a.w};
#pragma unroll
            for(int jj=0;jj<4;jj++){
                bool mm = m[jj]!=0;
#pragma unroll
                for(int h=0;h<4;h++){
                    float e = E[h] + ((const float*)&dv[h])[jj];
                    e = (e>0.f)?e:0.2f*e;
                    if(mm) S[h] += __expf(e);
                }
            }
            uint32_t nib = (m[0]?1u:0u)|(m[1]?2u:0u)|(m[2]?4u:0u)|(m[3]?8u:0u);
            bitsb[i*512 + q*8 + g] = (uint8_t)nib;
        }
#pragma unroll
        for(int h=0;h<4;h++)
#pragma unroll
            for(int o=1;o<8;o<<=1)
                S[h] += __shfl_xor_sync(0xffffffffu, S[h], o);
        if(g==0)
#pragma unroll
            for(int h=0;h<4;h++)
                iv[h*32+i] = (S[h] > 0.f) ? (1.f/S[h]) : 0.f;
    }
    __syncthreads();

    // ================= pass 2 setup =================
    // alpha task: one per thread
    const int th = tid>>6, tmb=(tid>>5)&1, tkb=(tid>>3)&3, tr=tid&7;
    const int iA = tmb*16 + tr;
    const float esA = es[th*32+iA],   esB = es[th*32+iA+8];
    const float ivA = iv[th*32+iA],   ivB = iv[th*32+iA+8];
    const float* edp = g_edst + (size_t)(b*Hh+th)*Nn + tkb*8;
    const uint8_t* bAp = bitsb + iA*512 + tkb*2;
    float* paA = alpha_out + ((size_t)((b*Hh+th)*Nn) + i0 + iA)*Nn + tkb*8;
    float* paB = paA + (size_t)8*Nn;
    const int fiA = (th*8 + tmb*4 + tkb)*32 + tr*4;
    // B stage: thread owns WhT row c = tid
    const float* whrow = g_WhT + ((size_t)(b*Dd + tid))*Nn;
    const int nb = tid>>3, lbase = (tid&7)*4;
    // MMA mapping
    const int wid = tid>>5, h_w = wid>>1, nh = wid&1;

    float acc[2][4][4];
#pragma unroll
    for(int m2=0;m2<2;m2++)
#pragma unroll
        for(int n2=0;n2<4;n2++)
#pragma unroll
            for(int q=0;q<4;q++) acc[m2][n2][q]=0.f;

    float4 Bp[8];
#pragma unroll
    for(int r=0;r<8;r++) Bp[r] = ((const float4*)whrow)[r];

    for(int t=0; t<NT; t++){
        const int j0 = t*TJ;
        // ---- alpha gen -> A frags + gmem ----
        {
            float4 e0 = *(const float4*)(edp + j0);
            float4 e1 = *(const float4*)(edp + j0 + 4);
            float ed[8]={e0.x,e0.y,e0.z,e0.w,e1.x,e1.y,e1.z,e1.w};
            uint32_t ua = (uint32_t)bAp[t*8] | ((uint32_t)bAp[t*8+1]<<4);
            uint32_t ub = (uint32_t)bAp[t*8+8*512] | ((uint32_t)bAp[t*8+1+8*512]<<4);
            float uAv[8], uBv[8];
#pragma unroll
            for(int jj=0;jj<8;jj++){
                float eA = esA + ed[jj]; eA = (eA>0.f)?eA:0.2f*eA;
                uAv[jj] = ((ua>>jj)&1u) ? __expf(eA)*ivA : 0.f;
                float eB = esB + ed[jj]; eB = (eB>0.f)?eB:0.2f*eB;
                uBv[jj] = ((ub>>jj)&1u) ? __expf(eB)*ivB : 0.f;
            }
            if(write_alpha){
                *(float4*)(paA + j0)   = make_float4(uAv[0],uAv[1],uAv[2],uAv[3]);
                *(float4*)(paA + j0+4) = make_float4(uAv[4],uAv[5],uAv[6],uAv[7]);
                *(float4*)(paB + j0)   = make_float4(uBv[0],uBv[1],uBv[2],uBv[3]);
                *(float4*)(paB + j0+4) = make_float4(uBv[4],uBv[5],uBv[6],uBv[7]);
            }
#pragma unroll
            for(int c=0;c<4;c++)
                As[fiA + c] = make_float4(totf(uAv[c]), totf(uBv[c]),
                                          totf(uAv[c+4]), totf(uBv[c+4]));
        }
        // ---- B frags from prefetched regs ----
        {
            float wv[32];
#pragma unroll
            for(int r=0;r<8;r++){ wv[r*4]=Bp[r].x; wv[r*4+1]=Bp[r].y;
                                  wv[r*4+2]=Bp[r].z; wv[r*4+3]=Bp[r].w; }
#pragma unroll
            for(int kb=0;kb<4;kb++)
#pragma unroll
                for(int rr=0;rr<4;rr++)
                    Bs2[(kb*32+nb)*33 + lbase + rr] =
                        make_float2(totf(wv[kb*8+rr]), totf(wv[kb*8+rr+4]));
        }
        __syncthreads();

        // ---- prefetch WhT tile t+1 ----
        if(t+1 < NT){
            const float4* src = (const float4*)(whrow + (t+1)*TJ);
#pragma unroll
            for(int r=0;r<8;r++) Bp[r] = src[r];
        }

        // ---- MMA ----
#pragma unroll
        for(int kb=0;kb<4;kb++){
            float4 av[2]; float2 bv[4];
#pragma unroll
            for(int m2=0;m2<2;m2++)
                av[m2] = As[(h_w*8 + m2*4 + kb)*32 + lane];
#pragma unroll
            for(int n2=0;n2<4;n2++)
                bv[n2] = Bs2[(kb*32 + h_w*8 + nh*4 + n2)*33 + lane];
#pragma unroll
            for(int m2=0;m2<2;m2++)
#pragma unroll
                for(int n2=0;n2<4;n2++)
                    mma8(acc[m2][n2], av[m2], bv[n2]);
        }
        __syncthreads();
    }

    // ---- epilogue ----
    const int cb = h_w*64 + nh*32;
    const int rl = lane>>2, cl = (lane&3)*2;
#pragma unroll
    for(int m2=0;m2<2;m2++){
        float* p0 = h_out + ((size_t)(b*Nn) + i0 + m2*16 + rl)*Dd + cb + cl;
        float* p1 = p0 + (size_t)8*Dd;
#pragma unroll
        for(int n2=0;n2<4;n2++){
            *(float2*)(p0 + n2*8) = make_float2(acc[m2][n2][0], acc[m2][n2][1]);
            *(float2*)(p1 + n2*8) = make_float2(acc[m2][n2][2], acc[m2][n2][3]);
        }
    }
}

// ---------------------------------------------------------------------------
extern "C" void kernel_launch(void* const* d_in, const int* in_sizes, int n_in,
                              void* d_out, int out_size){
    const float* h     = (const float*)d_in[0];
    const int*   adj   = (const int*)d_in[1];
    const float* W     = (const float*)d_in[2];
    const float* a_src = (const float*)d_in[3];
    const float* a_dst = (const float*)d_in[4];
    float* out = (float*)d_out;

    const long long houtN  = (long long)Bc*Nn*Dd;
    const long long alphaN = (long long)Bc*Hh*Nn*Nn;
    int write_alpha = ((long long)out_size >= houtN + alphaN) ? 1 : 0;
    float* alpha_out = out + houtN;

    cudaFuncSetAttribute(gat_main, cudaFuncAttributeMaxDynamicSharedMemorySize,
                         SMEM_MAIN);

    gemm_h_w<<<dim3(128,4),256>>>(h, W);
    gat_attn_proj<<<Bc*Hh*16,128>>>(a_src, a_dst);
    gat_main<<<Bc*64,256,SMEM_MAIN>>>(adj, out, alpha_out, write_alpha);
}

// round 7
// speedup vs baseline: 1.5511x; 1.5511x over previous
#include <cuda_runtime.h>
#include <cstdint>

constexpr int Bc=4, Nn=2048, Dd=256, Hh=4;
constexpr int TJ=32, NT=Nn/TJ;   // 64 k-tiles in gat_gemm

__device__ float g_Wh  [Bc*Nn*Dd];   // exact fp32, [b][j][c]
__device__ float g_WhR [Bc*Nn*Dd];   // tf32-rounded copy (B operand)
__device__ float g_esrc[Bc*Hh*Nn];
__device__ float g_edst[Bc*Hh*Nn];
__device__ float g_alpha_s[Bc*Hh*Nn*Nn];  // fallback if out buffer lacks alpha

__device__ __forceinline__ float totf(float x){
    uint32_t u; asm("cvt.rna.tf32.f32 %0, %1;" : "=r"(u) : "f"(x));
    return __uint_as_float(u);
}
__device__ __forceinline__ void mma8(float* d, float4 a, float2 b){
    asm volatile("mma.sync.aligned.m16n8k8.row.col.f32.tf32.tf32.f32 "
        "{%0,%1,%2,%3}, {%4,%5,%6,%7}, {%8,%9}, {%0,%1,%2,%3};"
        : "+f"(d[0]), "+f"(d[1]), "+f"(d[2]), "+f"(d[3])
        : "r"(__float_as_uint(a.x)), "r"(__float_as_uint(a.y)),
          "r"(__float_as_uint(a.z)), "r"(__float_as_uint(a.w)),
          "r"(__float_as_uint(b.x)), "r"(__float_as_uint(b.y)));
}
__device__ __forceinline__ void cpasync16(void* smem_p, const void* gmem){
    unsigned s = (unsigned)__cvta_generic_to_shared(smem_p);
    asm volatile("cp.async.cg.shared.global [%0], [%1], 16;" :: "r"(s), "l"(gmem));
}
#define CP_COMMIT() asm volatile("cp.async.commit_group;")

// ---------------------------------------------------------------------------
// K1: Wh = h @ W (fp32), normal layout; also writes tf32-rounded copy.
// ---------------------------------------------------------------------------
__global__ __launch_bounds__(256)
void gemm_h_w(const float* __restrict__ A, const float* __restrict__ Bw){
    __shared__ float As[16][64];
    __shared__ float Bs[16][64];
    const int tid=threadIdx.x;
    const int m0=blockIdx.x*64, n0=blockIdx.y*64;
    const int tm=tid>>4, tn=tid&15;
    const int lm=tid>>2, lk=(tid&3)*4;
    const int lbk=tid>>4, lbn=(tid&15)*4;
    float acc[4][4];
#pragma unroll
    for(int r=0;r<4;r++)
#pragma unroll
        for(int c=0;c<4;c++) acc[r][c]=0.f;
    for(int k0=0;k0<256;k0+=16){
        float4 av = *(const float4*)(A + (size_t)(m0+lm)*256 + k0+lk);
        As[lk+0][lm]=av.x; As[lk+1][lm]=av.y; As[lk+2][lm]=av.z; As[lk+3][lm]=av.w;
        *(float4*)&Bs[lbk][lbn] = *(const float4*)(Bw + (size_t)(k0+lbk)*256 + n0+lbn);
        __syncthreads();
#pragma unroll
        for(int k=0;k<16;k++){
            float4 a4=*(const float4*)&As[k][tm*4];
            float4 b4=*(const float4*)&Bs[k][tn*4];
            float ar[4]={a4.x,a4.y,a4.z,a4.w}, br[4]={b4.x,b4.y,b4.z,b4.w};
#pragma unroll
            for(int r=0;r<4;r++)
#pragma unroll
                for(int c=0;c<4;c++) acc[r][c]+=ar[r]*br[c];
        }
        __syncthreads();
    }
#pragma unroll
    for(int r=0;r<4;r++){
        size_t o = (size_t)(m0 + tm*4 + r)*256 + n0 + tn*4;
        *(float4*)(g_Wh + o) = make_float4(acc[r][0],acc[r][1],acc[r][2],acc[r][3]);
        *(float4*)(g_WhR + o) = make_float4(totf(acc[r][0]),totf(acc[r][1]),
                                            totf(acc[r][2]),totf(acc[r][3]));
    }
}

// ---------------------------------------------------------------------------
// K2: e_src/e_dst projections. One warp per (b,h,n).
// ---------------------------------------------------------------------------
__global__ __launch_bounds__(256)
void gat_attn_proj(const float* __restrict__ a_src, const float* __restrict__ a_dst){
    int r = blockIdx.x*8 + (threadIdx.x>>5);
    int lane = threadIdx.x & 31;
    int b = r>>13, h = (r>>11)&3, n = r & (Nn-1);
    const float* wp = g_Wh + ((size_t)(b*Nn+n))*Dd + h*64;
    float2 w  = *(const float2*)(wp + 2*lane);
    float2 as = *(const float2*)(a_src + h*64 + 2*lane);
    float2 ad = *(const float2*)(a_dst + h*64 + 2*lane);
    float ss = w.x*as.x + w.y*as.y;
    float sd = w.x*ad.x + w.y*ad.y;
#pragma unroll
    for(int o=16;o;o>>=1){
        ss += __shfl_xor_sync(0xffffffffu, ss, o);
        sd += __shfl_xor_sync(0xffffffffu, sd, o);
    }
    if(lane==0){ g_esrc[r]=ss; g_edst[r]=sd; }
}

// ---------------------------------------------------------------------------
// K3: alpha kernel (fused stats). Block = (b, 32 rows), 256 thr, ~8 CTA/SM.
// Pass1: adj -> smem nibble bits + row sums (no max-sub).
// Pass2: coalesced alpha stream-out.
// ---------------------------------------------------------------------------
__global__ __launch_bounds__(256)
void gat_alpha(const int* __restrict__ adj, float* __restrict__ alpha_out){
    __shared__ uint8_t bits[32*512];   // 16KB: [i][col/4] nibble
    __shared__ float es[128], iv[128]; // [h][i]
    const int tid = threadIdx.x;
    const int b  = blockIdx.x >> 6;
    const int i0 = (blockIdx.x & 63) * 32;

    if(tid<128) es[tid] = g_esrc[(b*Hh + (tid>>5))*Nn + i0 + (tid&31)];
    __syncthreads();

    // ---- pass 1 ----
    {
        const int i = tid>>3, g = tid&7;
        const int*   arow = adj + ((size_t)(b*Nn + i0 + i))*Nn + g*4;
        const float* edb  = g_edst + (size_t)(b*Hh)*Nn + g*4;
        float E[4] = {es[i], es[32+i], es[64+i], es[96+i]};
        float S[4] = {0.f,0.f,0.f,0.f};
#pragma unroll 2
        for(int q=0;q<64;q++){
            int4 a = *(const int4*)(arow + q*32);
            float4 dv[4];
#pragma unroll
            for(int h=0;h<4;h++)
                dv[h] = *(const float4*)(edb + (size_t)h*Nn + q*32);
            int m[4] = {a.x, a.y, a.z, a.w};
#pragma unroll
            for(int jj=0;jj<4;jj++){
                bool mm = m[jj]!=0;
#pragma unroll
                for(int h=0;h<4;h++){
                    float e = E[h] + ((const float*)&dv[h])[jj];
                    e = (e>0.f)?e:0.2f*e;
                    if(mm) S[h] += __expf(e);
                }
            }
            bits[i*512 + q*8 + g] =
                (uint8_t)((m[0]?1u:0u)|(m[1]?2u:0u)|(m[2]?4u:0u)|(m[3]?8u:0u));
        }
#pragma unroll
        for(int h=0;h<4;h++)
#pragma unroll
            for(int o=1;o<8;o<<=1)
                S[h] += __shfl_xor_sync(0xffffffffu, S[h], o);
        if(g==0)
#pragma unroll
            for(int h=0;h<4;h++)
                iv[h*32+i] = (S[h]>0.f) ? (1.f/S[h]) : 0.f;
    }
    __syncthreads();

    // ---- pass 2: stream alpha ----
    const int h = tid>>6, c = tid&63;
    const float* edp = g_edst + (size_t)(b*Hh+h)*Nn;
    float* ab = alpha_out + ((size_t)((b*Hh+h)*Nn) + i0)*Nn;
#pragma unroll
    for(int jc=0;jc<8;jc++){
        const int j = jc*256 + c*4;
        float4 ed = *(const float4*)(edp + j);
#pragma unroll 4
        for(int i=0;i<32;i++){
            float E = es[h*32+i], V = iv[h*32+i];
            uint32_t nib = bits[i*512 + (j>>2)];
            float4 o; float e;
            e=E+ed.x; e=(e>0.f)?e:0.2f*e; o.x = (nib&1u)?__expf(e)*V:0.f;
            e=E+ed.y; e=(e>0.f)?e:0.2f*e; o.y = (nib&2u)?__expf(e)*V:0.f;
            e=E+ed.z; e=(e>0.f)?e:0.2f*e; o.z = (nib&4u)?__expf(e)*V:0.f;
            e=E+ed.w; e=(e>0.f)?e:0.2f*e; o.w = (nib&8u)?__expf(e)*V:0.f;
            *(float4*)(ab + (size_t)i*Nn + j) = o;
        }
    }
}

// ---------------------------------------------------------------------------
// K4: h_out = alpha @ WhR per (b,h). Block = 128 rows x 64 cols, 256 thr.
// Double-buffered cp.async; m16n8k8 tf32 (fragment maps verified in R5).
// ---------------------------------------------------------------------------
constexpr int AST=36, BST=72;          // padded strides (floats)
constexpr int ABUF=128*AST, BBUF=32*BST;
constexpr int SMEM_K4 = (2*ABUF + 2*BBUF)*4;   // 55296 B

__global__ __launch_bounds__(256,2)
void gat_gemm(const float* __restrict__ alpha, float* __restrict__ h_out){
    extern __shared__ float sm[];
    float* Aa[2] = { sm, sm + ABUF };
    float* Bb[2] = { sm + 2*ABUF, sm + 2*ABUF + BBUF };

    const int tid = threadIdx.x, lane = tid & 31;
    const int bh = blockIdx.y, b = bh>>2, h = bh&3;
    const int i0 = blockIdx.x * 128;
    const float* abase = alpha + ((size_t)bh*Nn + i0)*Nn;
    const float* wbase = g_WhR + (size_t)b*Nn*Dd + h*64;

    const int mq = (tid>>5)&3, nq = tid>>7;   // warp: rows mq*32, cols nq*32

    float acc[2][4][4];
#pragma unroll
    for(int mf=0;mf<2;mf++)
#pragma unroll
        for(int nf=0;nf<4;nf++)
#pragma unroll
            for(int q=0;q<4;q++) acc[mf][nf][q]=0.f;

    // staging maps
    const int a_row = tid>>3, a_ch = tid&7;          // +k*32 rows (k<4)
    const int b_j   = tid>>4, b_ch = tid&15;         // +k*16 rows (k<2)

    auto stage = [&](int t, int buf){
        const int j0 = t*TJ;
        float* Asm = Aa[buf];
        float* Bsm = Bb[buf];
#pragma unroll
        for(int k=0;k<4;k++){
            int row = a_row + k*32;
            cpasync16(Asm + row*AST + a_ch*4,
                      abase + (size_t)row*Nn + j0 + a_ch*4);
        }
#pragma unroll
        for(int k=0;k<2;k++){
            int j = b_j + k*16;
            cpasync16(Bsm + j*BST + b_ch*4,
                      wbase + (size_t)(j0+j)*Dd + b_ch*4);
        }
    };

    stage(0,0); CP_COMMIT();

    for(int t=0;t<NT;t++){
        if(t+1 < NT){
            stage(t+1, (t+1)&1); CP_COMMIT();
            asm volatile("cp.async.wait_group 1;");
        } else {
            asm volatile("cp.async.wait_group 0;");
        }
        __syncthreads();
        const float* As = Aa[t&1];
        const float* Bs = Bb[t&1];
#pragma unroll
        for(int kb=0;kb<4;kb++){
            float4 av[2];
#pragma unroll
            for(int mf=0;mf<2;mf++){
                int r = mq*32 + mf*16 + (lane>>2);
                int c = kb*8 + (lane&3);
                av[mf] = make_float4(totf(As[r*AST + c]),
                                     totf(As[(r+8)*AST + c]),
                                     totf(As[r*AST + c+4]),
                                     totf(As[(r+8)*AST + c+4]));
            }
            float2 bv[4];
#pragma unroll
            for(int nf=0;nf<4;nf++){
                int bj = (kb*8 + (lane&3))*BST + nq*32 + nf*8 + (lane>>2);
                bv[nf] = make_float2(Bs[bj], Bs[bj + 4*BST]);
            }
#pragma unroll
            for(int mf=0;mf<2;mf++)
#pragma unroll
                for(int nf=0;nf<4;nf++)
                    mma8(acc[mf][nf], av[mf], bv[nf]);
        }
        __syncthreads();
    }

    // epilogue
    const int r0 = i0 + mq*32, c0 = h*64 + nq*32;
#pragma unroll
    for(int mf=0;mf<2;mf++){
        int row = r0 + mf*16 + (lane>>2);
        float* p0 = h_out + ((size_t)(b*Nn) + row)*Dd + c0 + (lane&3)*2;
        float* p1 = p0 + (size_t)8*Dd;
#pragma unroll
        for(int nf=0;nf<4;nf++){
            *(float2*)(p0 + nf*8) = make_float2(acc[mf][nf][0], acc[mf][nf][1]);
            *(float2*)(p1 + nf*8) = make_float2(acc[mf][nf][2], acc[mf][nf][3]);
        }
    }
}

// ---------------------------------------------------------------------------
extern "C" void kernel_launch(void* const* d_in, const int* in_sizes, int n_in,
                              void* d_out, int out_size){
    const float* h     = (const float*)d_in[0];
    const int*   adj   = (const int*)d_in[1];
    const float* W     = (const float*)d_in[2];
    const float* a_src = (const float*)d_in[3];
    const float* a_dst = (const float*)d_in[4];
    float* out = (float*)d_out;

    const long long houtN  = (long long)Bc*Nn*Dd;
    const long long alphaN = (long long)Bc*Hh*Nn*Nn;
    bool has_alpha = ((long long)out_size >= houtN + alphaN);
    float* alpha_buf;
    if(has_alpha){
        alpha_buf = out + houtN;
    } else {
        cudaGetSymbolAddress((void**)&alpha_buf, g_alpha_s);
    }

    cudaFuncSetAttribute(gat_gemm, cudaFuncAttributeMaxDynamicSharedMemorySize,
                         SMEM_K4);

    gemm_h_w<<<dim3(128,4),256>>>(h, W);
    gat_attn_proj<<<(Bc*Hh*Nn)/8,256>>>(a_src, a_dst);
    gat_alpha<<<Bc*64,256>>>(adj, alpha_buf);
    gat_gemm<<<dim3(16,16),256,SMEM_K4>>>(alpha_buf, out);
}

// round 8
// speedup vs baseline: 1.7687x; 1.1403x over previous
#include <cuda_runtime.h>
#include <cstdint>

constexpr int Bc=4, Nn=2048, Dd=256, Hh=4;
constexpr int TJ=32, NT=Nn/TJ;   // 64 k-tiles in gat_gemm

__device__ float g_Wh  [Bc*Nn*Dd];   // exact fp32, [b][j][c]
__device__ float g_WhR [Bc*Nn*Dd];   // tf32-rounded copy (B operand)
__device__ float g_esrc[Bc*Hh*Nn];
__device__ float g_edst[Bc*Hh*Nn];
__device__ float g_alpha_s[Bc*Hh*Nn*Nn];  // fallback if out buffer lacks alpha

__device__ __forceinline__ float totf(float x){
    uint32_t u; asm("cvt.rna.tf32.f32 %0, %1;" : "=r"(u) : "f"(x));
    return __uint_as_float(u);
}
__device__ __forceinline__ float2 ffma2f(float a, float2 w, float2 c){
    union U { float2 f2; unsigned long long u; };
    U ua, uw, uc, ud;
    ua.f2 = make_float2(a, a); uw.f2 = w; uc.f2 = c;
    asm("fma.rn.f32x2 %0, %1, %2, %3;" : "=l"(ud.u) : "l"(ua.u), "l"(uw.u), "l"(uc.u));
    return ud.f2;
}
__device__ __forceinline__ void mma8(float* d, float4 a, float2 b){
    asm volatile("mma.sync.aligned.m16n8k8.row.col.f32.tf32.tf32.f32 "
        "{%0,%1,%2,%3}, {%4,%5,%6,%7}, {%8,%9}, {%0,%1,%2,%3};"
        : "+f"(d[0]), "+f"(d[1]), "+f"(d[2]), "+f"(d[3])
        : "r"(__float_as_uint(a.x)), "r"(__float_as_uint(a.y)),
          "r"(__float_as_uint(a.z)), "r"(__float_as_uint(a.w)),
          "r"(__float_as_uint(b.x)), "r"(__float_as_uint(b.y)));
}
__device__ __forceinline__ void cpasync16(void* smem_p, const void* gmem){
    unsigned s = (unsigned)__cvta_generic_to_shared(smem_p);
    asm volatile("cp.async.cg.shared.global [%0], [%1], 16;" :: "r"(s), "l"(gmem));
}
#define CP_COMMIT() asm volatile("cp.async.commit_group;")

// ---------------------------------------------------------------------------
// K1: Wh = h @ W (fp32, packed ffma2 accum); writes exact + tf32-rounded copy.
// ---------------------------------------------------------------------------
__global__ __launch_bounds__(256)
void gemm_h_w(const float* __restrict__ A, const float* __restrict__ Bw){
    __shared__ float As[16][64];
    __shared__ float Bs[16][64];
    const int tid=threadIdx.x;
    const int m0=blockIdx.x*64, n0=blockIdx.y*64;
    const int tm=tid>>4, tn=tid&15;
    const int lm=tid>>2, lk=(tid&3)*4;
    const int lbk=tid>>4, lbn=(tid&15)*4;
    float2 acc[4][2];
#pragma unroll
    for(int r=0;r<4;r++){ acc[r][0]=make_float2(0.f,0.f); acc[r][1]=make_float2(0.f,0.f); }
    for(int k0=0;k0<256;k0+=16){
        float4 av = *(const float4*)(A + (size_t)(m0+lm)*256 + k0+lk);
        As[lk+0][lm]=av.x; As[lk+1][lm]=av.y; As[lk+2][lm]=av.z; As[lk+3][lm]=av.w;
        *(float4*)&Bs[lbk][lbn] = *(const float4*)(Bw + (size_t)(k0+lbk)*256 + n0+lbn);
        __syncthreads();
#pragma unroll
        for(int k=0;k<16;k++){
            float4 a4=*(const float4*)&As[k][tm*4];
            float4 b4=*(const float4*)&Bs[k][tn*4];
            float ar[4]={a4.x,a4.y,a4.z,a4.w};
            float2 b01=make_float2(b4.x,b4.y), b23=make_float2(b4.z,b4.w);
#pragma unroll
            for(int r=0;r<4;r++){
                acc[r][0]=ffma2f(ar[r], b01, acc[r][0]);
                acc[r][1]=ffma2f(ar[r], b23, acc[r][1]);
            }
        }
        __syncthreads();
    }
#pragma unroll
    for(int r=0;r<4;r++){
        size_t o = (size_t)(m0 + tm*4 + r)*256 + n0 + tn*4;
        *(float4*)(g_Wh + o) = make_float4(acc[r][0].x,acc[r][0].y,acc[r][1].x,acc[r][1].y);
        *(float4*)(g_WhR + o) = make_float4(totf(acc[r][0].x),totf(acc[r][0].y),
                                            totf(acc[r][1].x),totf(acc[r][1].y));
    }
}

// ---------------------------------------------------------------------------
// K2: e_src/e_dst projections. One warp per (b,h,n).
// ---------------------------------------------------------------------------
__global__ __launch_bounds__(256)
void gat_attn_proj(const float* __restrict__ a_src, const float* __restrict__ a_dst){
    int r = blockIdx.x*8 + (threadIdx.x>>5);
    int lane = threadIdx.x & 31;
    int b = r>>13, h = (r>>11)&3, n = r & (Nn-1);
    const float* wp = g_Wh + ((size_t)(b*Nn+n))*Dd + h*64;
    float2 w  = *(const float2*)(wp + 2*lane);
    float2 as = *(const float2*)(a_src + h*64 + 2*lane);
    float2 ad = *(const float2*)(a_dst + h*64 + 2*lane);
    float ss = w.x*as.x + w.y*as.y;
    float sd = w.x*ad.x + w.y*ad.y;
#pragma unroll
    for(int o=16;o;o>>=1){
        ss += __shfl_xor_sync(0xffffffffu, ss, o);
        sd += __shfl_xor_sync(0xffffffffu, sd, o);
    }
    if(lane==0){ g_esrc[r]=ss; g_edst[r]=sd; }
}

// ---------------------------------------------------------------------------
// K3: alpha kernel. Block = (b, 8 rows), grid 1024, 256 thr.
// Pass1: one warp per row: adj -> nibble bits + row sums (no max-sub).
// Pass2: coalesced alpha stream-out.
// ---------------------------------------------------------------------------
__global__ __launch_bounds__(256)
void gat_alpha(const int* __restrict__ adj, float* __restrict__ alpha_out){
    __shared__ uint8_t bits[8*512];    // 4KB: [i][col/4] nibble
    __shared__ float es[32], iv[32];   // [h][i]  (h*8+i)
    const int tid = threadIdx.x;
    const int b  = blockIdx.x >> 8;
    const int i0 = (blockIdx.x & 255) * 8;

    if(tid<32) es[tid] = g_esrc[(b*Hh + (tid>>3))*Nn + i0 + (tid&7)];
    __syncthreads();

    // ---- pass 1: warp w owns row i=w ----
    {
        const int i = tid>>5, g = tid&31;
        const int*   arow = adj + ((size_t)(b*Nn + i0 + i))*Nn + g*4;
        const float* edb  = g_edst + (size_t)(b*Hh)*Nn + g*4;
        float E[4] = {es[i], es[8+i], es[16+i], es[24+i]};
        float S[4] = {0.f,0.f,0.f,0.f};
#pragma unroll 4
        for(int q=0;q<16;q++){
            int4 a = *(const int4*)(arow + q*128);
            float4 dv[4];
#pragma unroll
            for(int h=0;h<4;h++)
                dv[h] = *(const float4*)(edb + (size_t)h*Nn + q*128);
            int m[4] = {a.x, a.y, a.z, a.w};
#pragma unroll
            for(int jj=0;jj<4;jj++){
                bool mm = m[jj]!=0;
#pragma unroll
                for(int h=0;h<4;h++){
                    float e = E[h] + ((const float*)&dv[h])[jj];
                    e = (e>0.f)?e:0.2f*e;
                    if(mm) S[h] += __expf(e);
                }
            }
            bits[i*512 + q*32 + g] =
                (uint8_t)((m[0]?1u:0u)|(m[1]?2u:0u)|(m[2]?4u:0u)|(m[3]?8u:0u));
        }
#pragma unroll
        for(int h=0;h<4;h++)
#pragma unroll
            for(int o=16;o;o>>=1)
                S[h] += __shfl_xor_sync(0xffffffffu, S[h], o);
        if(g==0)
#pragma unroll
            for(int h=0;h<4;h++)
                iv[h*8+i] = (S[h]>0.f) ? (1.f/S[h]) : 0.f;
    }
    __syncthreads();

    // ---- pass 2: stream alpha, h = tid>>6, 64 j-lanes ----
    const int h = tid>>6, c = tid&63;
    const float* edp = g_edst + (size_t)(b*Hh+h)*Nn;
    float* ab = alpha_out + ((size_t)((b*Hh+h)*Nn) + i0)*Nn;
    const float* esh = es + h*8;
    const float* ivh = iv + h*8;
#pragma unroll
    for(int jc=0;jc<8;jc++){
        const int j = jc*256 + c*4;
        float4 ed = *(const float4*)(edp + j);
#pragma unroll
        for(int i=0;i<8;i++){
            float E = esh[i], V = ivh[i];
            uint32_t nib = bits[i*512 + (j>>2)];
            float4 o; float e;
            e=E+ed.x; e=(e>0.f)?e:0.2f*e; o.x = (nib&1u)?__expf(e)*V:0.f;
            e=E+ed.y; e=(e>0.f)?e:0.2f*e; o.y = (nib&2u)?__expf(e)*V:0.f;
            e=E+ed.z; e=(e>0.f)?e:0.2f*e; o.z = (nib&4u)?__expf(e)*V:0.f;
            e=E+ed.w; e=(e>0.f)?e:0.2f*e; o.w = (nib&8u)?__expf(e)*V:0.f;
            *(float4*)(ab + (size_t)i*Nn + j) = o;
        }
    }
}

// ---------------------------------------------------------------------------
// K4: h_out = alpha @ WhR per (b,h). Block = 64 rows x 64 cols, 256 thr,
// grid (32,16). A fed raw fp32 (HW tf32 truncation); B pre-rounded RNA.
// ---------------------------------------------------------------------------
constexpr int AST=36, BST=72;
constexpr int ABUF=64*AST, BBUF=32*BST;         // 2304 + 2304 floats
constexpr int SMEM_K4 = (2*ABUF + 2*BBUF)*4;    // 36864 B

__global__ __launch_bounds__(256,3)
void gat_gemm(const float* __restrict__ alpha, float* __restrict__ h_out){
    extern __shared__ float sm[];
    float* Aa[2] = { sm, sm + ABUF };
    float* Bb[2] = { sm + 2*ABUF, sm + 2*ABUF + BBUF };

    const int tid = threadIdx.x, lane = tid & 31;
    const int bh = blockIdx.y, b = bh>>2, h = bh&3;
    const int i0 = blockIdx.x * 64;
    const float* abase = alpha + ((size_t)bh*Nn + i0)*Nn;
    const float* wbase = g_WhR + (size_t)b*Nn*Dd + h*64;

    const int wid = tid>>5;
    const int mq = wid&3, nq = wid>>2;   // warp: rows mq*16, cols nq*32

    float acc[4][4];
#pragma unroll
    for(int nf=0;nf<4;nf++)
#pragma unroll
        for(int q=0;q<4;q++) acc[nf][q]=0.f;

    // staging maps
    const int a_row = tid>>3, a_ch = tid&7;    // 32 rows/pass, 2 passes
    const int b_j   = tid>>4, b_ch = tid&15;   // 16 j/pass, 2 passes

    auto stage = [&](int t, int buf){
        const int j0 = t*TJ;
        float* Asm = Aa[buf];
        float* Bsm = Bb[buf];
#pragma unroll
        for(int k=0;k<2;k++){
            int row = a_row + k*32;
            cpasync16(Asm + row*AST + a_ch*4,
                      abase + (size_t)row*Nn + j0 + a_ch*4);
        }
#pragma unroll
        for(int k=0;k<2;k++){
            int j = b_j + k*16;
            cpasync16(Bsm + j*BST + b_ch*4,
                      wbase + (size_t)(j0+j)*Dd + b_ch*4);
        }
    };

    stage(0,0); CP_COMMIT();

    for(int t=0;t<NT;t++){
        if(t+1 < NT){
            stage(t+1, (t+1)&1); CP_COMMIT();
            asm volatile("cp.async.wait_group 1;");
        } else {
            asm volatile("cp.async.wait_group 0;");
        }
        __syncthreads();
        const float* As = Aa[t&1];
        const float* Bs = Bb[t&1];
#pragma unroll
        for(int kb=0;kb<4;kb++){
            const int r = mq*16 + (lane>>2);
            const int c = kb*8 + (lane&3);
            float4 av = make_float4(As[r*AST + c],     As[(r+8)*AST + c],
                                    As[r*AST + c + 4], As[(r+8)*AST + c + 4]);
            float2 bv[4];
#pragma unroll
            for(int nf=0;nf<4;nf++){
                int bj = (kb*8 + (lane&3))*BST + nq*32 + nf*8 + (lane>>2);
                bv[nf] = make_float2(Bs[bj], Bs[bj + 4*BST]);
            }
#pragma unroll
            for(int nf=0;nf<4;nf++)
                mma8(acc[nf], av, bv[nf]);
        }
        __syncthreads();
    }

    // epilogue
    const int row = i0 + mq*16 + (lane>>2);
    const int c0  = h*64 + nq*32 + (lane&3)*2;
    float* p0 = h_out + ((size_t)(b*Nn) + row)*Dd + c0;
    float* p1 = p0 + (size_t)8*Dd;
#pragma unroll
    for(int nf=0;nf<4;nf++){
        *(float2*)(p0 + nf*8) = make_float2(acc[nf][0], acc[nf][1]);
        *(float2*)(p1 + nf*8) = make_float2(acc[nf][2], acc[nf][3]);
    }
}

// ---------------------------------------------------------------------------
extern "C" void kernel_launch(void* const* d_in, const int* in_sizes, int n_in,
                              void* d_out, int out_size){
    const float* h     = (const float*)d_in[0];
    const int*   adj   = (const int*)d_in[1];
    const float* W     = (const float*)d_in[2];
    const float* a_src = (const float*)d_in[3];
    const float* a_dst = (const float*)d_in[4];
    float* out = (float*)d_out;

    const long long houtN  = (long long)Bc*Nn*Dd;
    const long long alphaN = (long long)Bc*Hh*Nn*Nn;
    bool has_alpha = ((long long)out_size >= houtN + alphaN);
    float* alpha_buf;
    if(has_alpha){
        alpha_buf = out + houtN;
    } else {
        cudaGetSymbolAddress((void**)&alpha_buf, g_alpha_s);
    }

    cudaFuncSetAttribute(gat_gemm, cudaFuncAttributeMaxDynamicSharedMemorySize,
                         SMEM_K4);

    gemm_h_w<<<dim3(128,4),256>>>(h, W);
    gat_attn_proj<<<(Bc*Hh*Nn)/8,256>>>(a_src, a_dst);
    gat_alpha<<<Bc*256,256>>>(adj, alpha_buf);
    gat_gemm<<<dim3(32,16),256,SMEM_K4>>>(alpha_buf, out);
}

// round 9
// speedup vs baseline: 2.0560x; 1.1624x over previous
#include <cuda_runtime.h>
#include <cstdint>

constexpr int Bc=4, Nn=2048, Dd=256, Hh=4;
constexpr int TJ=32, NT=Nn/TJ;   // 64 k-tiles in gat_gemm

__device__ float g_Wh  [Bc*Nn*Dd];   // exact fp32, [b][j][c]
__device__ float g_WhR [Bc*Nn*Dd];   // tf32-rounded copy (B operand)
__device__ float g_esrc[Bc*Hh*Nn];
__device__ float g_edst[Bc*Hh*Nn];
__device__ float g_alpha_s[Bc*Hh*Nn*Nn];  // fallback if out buffer lacks alpha

__device__ __forceinline__ float totf(float x){
    uint32_t u; asm("cvt.rna.tf32.f32 %0, %1;" : "=r"(u) : "f"(x));
    return __uint_as_float(u);
}
__device__ __forceinline__ float2 ffma2f(float a, float2 w, float2 c){
    union U { float2 f2; unsigned long long u; };
    U ua, uw, uc, ud;
    ua.f2 = make_float2(a, a); uw.f2 = w; uc.f2 = c;
    asm("fma.rn.f32x2 %0, %1, %2, %3;" : "=l"(ud.u) : "l"(ua.u), "l"(uw.u), "l"(uc.u));
    return ud.f2;
}
__device__ __forceinline__ void mma8(float* d, float4 a, float2 b){
    asm volatile("mma.sync.aligned.m16n8k8.row.col.f32.tf32.tf32.f32 "
        "{%0,%1,%2,%3}, {%4,%5,%6,%7}, {%8,%9}, {%0,%1,%2,%3};"
        : "+f"(d[0]), "+f"(d[1]), "+f"(d[2]), "+f"(d[3])
        : "r"(__float_as_uint(a.x)), "r"(__float_as_uint(a.y)),
          "r"(__float_as_uint(a.z)), "r"(__float_as_uint(a.w)),
          "r"(__float_as_uint(b.x)), "r"(__float_as_uint(b.y)));
}
__device__ __forceinline__ void cpasync16(void* smem_p, const void* gmem){
    unsigned s = (unsigned)__cvta_generic_to_shared(smem_p);
    asm volatile("cp.async.cg.shared.global [%0], [%1], 16;" :: "r"(s), "l"(gmem));
}
#define CP_COMMIT() asm volatile("cp.async.commit_group;")

// ---------------------------------------------------------------------------
// K1: Wh = h @ W (fp32, packed ffma2 accum); writes exact + tf32-rounded copy.
// ---------------------------------------------------------------------------
__global__ __launch_bounds__(256)
void gemm_h_w(const float* __restrict__ A, const float* __restrict__ Bw){
    __shared__ float As[16][64];
    __shared__ float Bs[16][64];
    const int tid=threadIdx.x;
    const int m0=blockIdx.x*64, n0=blockIdx.y*64;
    const int tm=tid>>4, tn=tid&15;
    const int lm=tid>>2, lk=(tid&3)*4;
    const int lbk=tid>>4, lbn=(tid&15)*4;
    float2 acc[4][2];
#pragma unroll
    for(int r=0;r<4;r++){ acc[r][0]=make_float2(0.f,0.f); acc[r][1]=make_float2(0.f,0.f); }
    for(int k0=0;k0<256;k0+=16){
        float4 av = *(const float4*)(A + (size_t)(m0+lm)*256 + k0+lk);
        As[lk+0][lm]=av.x; As[lk+1][lm]=av.y; As[lk+2][lm]=av.z; As[lk+3][lm]=av.w;
        *(float4*)&Bs[lbk][lbn] = *(const float4*)(Bw + (size_t)(k0+lbk)*256 + n0+lbn);
        __syncthreads();
#pragma unroll
        for(int k=0;k<16;k++){
            float4 a4=*(const float4*)&As[k][tm*4];
            float4 b4=*(const float4*)&Bs[k][tn*4];
            float ar[4]={a4.x,a4.y,a4.z,a4.w};
            float2 b01=make_float2(b4.x,b4.y), b23=make_float2(b4.z,b4.w);
#pragma unroll
            for(int r=0;r<4;r++){
                acc[r][0]=ffma2f(ar[r], b01, acc[r][0]);
                acc[r][1]=ffma2f(ar[r], b23, acc[r][1]);
            }
        }
        __syncthreads();
    }
#pragma unroll
    for(int r=0;r<4;r++){
        size_t o = (size_t)(m0 + tm*4 + r)*256 + n0 + tn*4;
        *(float4*)(g_Wh + o) = make_float4(acc[r][0].x,acc[r][0].y,acc[r][1].x,acc[r][1].y);
        *(float4*)(g_WhR + o) = make_float4(totf(acc[r][0].x),totf(acc[r][0].y),
                                            totf(acc[r][1].x),totf(acc[r][1].y));
    }
}

// ---------------------------------------------------------------------------
// K2: e_src/e_dst projections. One warp per (b,h,n).
// ---------------------------------------------------------------------------
__global__ __launch_bounds__(256)
void gat_attn_proj(const float* __restrict__ a_src, const float* __restrict__ a_dst){
    int r = blockIdx.x*8 + (threadIdx.x>>5);
    int lane = threadIdx.x & 31;
    int b = r>>13, h = (r>>11)&3, n = r & (Nn-1);
    const float* wp = g_Wh + ((size_t)(b*Nn+n))*Dd + h*64;
    float2 w  = *(const float2*)(wp + 2*lane);
    float2 as = *(const float2*)(a_src + h*64 + 2*lane);
    float2 ad = *(const float2*)(a_dst + h*64 + 2*lane);
    float ss = w.x*as.x + w.y*as.y;
    float sd = w.x*ad.x + w.y*ad.y;
#pragma unroll
    for(int o=16;o;o>>=1){
        ss += __shfl_xor_sync(0xffffffffu, ss, o);
        sd += __shfl_xor_sync(0xffffffffu, sd, o);
    }
    if(lane==0){ g_esrc[r]=ss; g_edst[r]=sd; }
}

// ---------------------------------------------------------------------------
// K3: alpha kernel. Block = (b, 8 rows), grid 1024, 256 thr. (at roofline)
// ---------------------------------------------------------------------------
__global__ __launch_bounds__(256)
void gat_alpha(const int* __restrict__ adj, float* __restrict__ alpha_out){
    __shared__ uint8_t bits[8*512];    // 4KB
    __shared__ float es[32], iv[32];
    const int tid = threadIdx.x;
    const int b  = blockIdx.x >> 8;
    const int i0 = (blockIdx.x & 255) * 8;

    if(tid<32) es[tid] = g_esrc[(b*Hh + (tid>>3))*Nn + i0 + (tid&7)];
    __syncthreads();

    {
        const int i = tid>>5, g = tid&31;
        const int*   arow = adj + ((size_t)(b*Nn + i0 + i))*Nn + g*4;
        const float* edb  = g_edst + (size_t)(b*Hh)*Nn + g*4;
        float E[4] = {es[i], es[8+i], es[16+i], es[24+i]};
        float S[4] = {0.f,0.f,0.f,0.f};
#pragma unroll 4
        for(int q=0;q<16;q++){
            int4 a = *(const int4*)(arow + q*128);
            float4 dv[4];
#pragma unroll
            for(int h=0;h<4;h++)
                dv[h] = *(const float4*)(edb + (size_t)h*Nn + q*128);
            int m[4] = {a.x, a.y, a.z, a.w};
#pragma unroll
            for(int jj=0;jj<4;jj++){
                bool mm = m[jj]!=0;
#pragma unroll
                for(int h=0;h<4;h++){
                    float e = E[h] + ((const float*)&dv[h])[jj];
                    e = (e>0.f)?e:0.2f*e;
                    if(mm) S[h] += __expf(e);
                }
            }
            bits[i*512 + q*32 + g] =
                (uint8_t)((m[0]?1u:0u)|(m[1]?2u:0u)|(m[2]?4u:0u)|(m[3]?8u:0u));
        }
#pragma unroll
        for(int h=0;h<4;h++)
#pragma unroll
            for(int o=16;o;o>>=1)
                S[h] += __shfl_xor_sync(0xffffffffu, S[h], o);
        if(g==0)
#pragma unroll
            for(int h=0;h<4;h++)
                iv[h*8+i] = (S[h]>0.f) ? (1.f/S[h]) : 0.f;
    }
    __syncthreads();

    const int h = tid>>6, c = tid&63;
    const float* edp = g_edst + (size_t)(b*Hh+h)*Nn;
    float* ab = alpha_out + ((size_t)((b*Hh+h)*Nn) + i0)*Nn;
    const float* esh = es + h*8;
    const float* ivh = iv + h*8;
#pragma unroll
    for(int jc=0;jc<8;jc++){
        const int j = jc*256 + c*4;
        float4 ed = *(const float4*)(edp + j);
#pragma unroll
        for(int i=0;i<8;i++){
            float E = esh[i], V = ivh[i];
            uint32_t nib = bits[i*512 + (j>>2)];
            float4 o; float e;
            e=E+ed.x; e=(e>0.f)?e:0.2f*e; o.x = (nib&1u)?__expf(e)*V:0.f;
            e=E+ed.y; e=(e>0.f)?e:0.2f*e; o.y = (nib&2u)?__expf(e)*V:0.f;
            e=E+ed.z; e=(e>0.f)?e:0.2f*e; o.z = (nib&4u)?__expf(e)*V:0.f;
            e=E+ed.w; e=(e>0.f)?e:0.2f*e; o.w = (nib&8u)?__expf(e)*V:0.f;
            *(float4*)(ab + (size_t)i*Nn + j) = o;
        }
    }
}

// ---------------------------------------------------------------------------
// K4: h_out = alpha @ WhR per (b,h). M=128 tiles, 4-stage cp.async pipeline.
// grid (16,16), 256 thr, 2 CTA/SM. A raw fp32 (HW tf32 trunc), B pre-rounded.
// ---------------------------------------------------------------------------
constexpr int AST=36, BST=72;
constexpr int ABUF=128*AST, BBUF=32*BST;          // 4608 + 2304 floats/stage
constexpr int STG = ABUF + BBUF;                  // 6912 floats = 27648 B
constexpr int SMEM_K4 = 4*STG*4;                  // 110592 B

__global__ __launch_bounds__(256,2)
void gat_gemm(const float* __restrict__ alpha, float* __restrict__ h_out){
    extern __shared__ float sm[];

    const int tid = threadIdx.x, lane = tid & 31;
    const int bh = blockIdx.y, b = bh>>2, h = bh&3;
    const int i0 = blockIdx.x * 128;
    const float* abase = alpha + ((size_t)bh*Nn + i0)*Nn;
    const float* wbase = g_WhR + (size_t)b*Nn*Dd + h*64;

    const int mq = (tid>>5)&3, nq = tid>>7;   // warp: rows mq*32, cols nq*32

    float acc[2][4][4];
#pragma unroll
    for(int mf=0;mf<2;mf++)
#pragma unroll
        for(int nf=0;nf<4;nf++)
#pragma unroll
            for(int q=0;q<4;q++) acc[mf][nf][q]=0.f;

    const int a_row = tid>>3, a_ch = tid&7;    // 32 rows/pass, 4 passes
    const int b_j   = tid>>4, b_ch = tid&15;   // 16 j/pass, 2 passes

    auto stage = [&](int t){
        const int j0 = t*TJ;
        float* Asm = sm + (t&3)*STG;
        float* Bsm = Asm + ABUF;
#pragma unroll
        for(int k=0;k<4;k++){
            int row = a_row + k*32;
            cpasync16(Asm + row*AST + a_ch*4,
                      abase + (size_t)row*Nn + j0 + a_ch*4);
        }
#pragma unroll
        for(int k=0;k<2;k++){
            int j = b_j + k*16;
            cpasync16(Bsm + j*BST + b_ch*4,
                      wbase + (size_t)(j0+j)*Dd + b_ch*4);
        }
        CP_COMMIT();
    };

    stage(0); stage(1); stage(2);

    for(int t=0;t<NT;t++){
        asm volatile("cp.async.wait_group 2;");
        __syncthreads();
        if(t+3 < NT) stage(t+3);
        const float* As = sm + (t&3)*STG;
        const float* Bs = As + ABUF;
#pragma unroll
        for(int kb=0;kb<4;kb++){
            float4 av[2];
#pragma unroll
            for(int mf=0;mf<2;mf++){
                int r = mq*32 + mf*16 + (lane>>2);
                int c = kb*8 + (lane&3);
                av[mf] = make_float4(As[r*AST + c],     As[(r+8)*AST + c],
                                     As[r*AST + c + 4], As[(r+8)*AST + c + 4]);
            }
            float2 bv[4];
#pragma unroll
            for(int nf=0;nf<4;nf++){
                int bj = (kb*8 + (lane&3))*BST + nq*32 + nf*8 + (lane>>2);
                bv[nf] = make_float2(Bs[bj], Bs[bj + 4*BST]);
            }
#pragma unroll
            for(int mf=0;mf<2;mf++)
#pragma unroll
                for(int nf=0;nf<4;nf++)
                    mma8(acc[mf][nf], av[mf], bv[nf]);
        }
        __syncthreads();
    }

    // epilogue
    const int r0 = i0 + mq*32, c0 = h*64 + nq*32;
#pragma unroll
    for(int mf=0;mf<2;mf++){
        int row = r0 + mf*16 + (lane>>2);
        float* p0 = h_out + ((size_t)(b*Nn) + row)*Dd + c0 + (lane&3)*2;
        float* p1 = p0 + (size_t)8*Dd;
#pragma unroll
        for(int nf=0;nf<4;nf++){
            *(float2*)(p0 + nf*8) = make_float2(acc[mf][nf][0], acc[mf][nf][1]);
            *(float2*)(p1 + nf*8) = make_float2(acc[mf][nf][2], acc[mf][nf][3]);
        }
    }
}

// ---------------------------------------------------------------------------
extern "C" void kernel_launch(void* const* d_in, const int* in_sizes, int n_in,
                              void* d_out, int out_size){
    const float* h     = (const float*)d_in[0];
    const int*   adj   = (const int*)d_in[1];
    const float* W     = (const float*)d_in[2];
    const float* a_src = (const float*)d_in[3];
    const float* a_dst = (const float*)d_in[4];
    float* out = (float*)d_out;

    const long long houtN  = (long long)Bc*Nn*Dd;
    const long long alphaN = (long long)Bc*Hh*Nn*Nn;
    bool has_alpha = ((long long)out_size >= houtN + alphaN);
    float* alpha_buf;
    if(has_alpha){
        alpha_buf = out + houtN;
    } else {
        cudaGetSymbolAddress((void**)&alpha_buf, g_alpha_s);
    }

    cudaFuncSetAttribute(gat_gemm, cudaFuncAttributeMaxDynamicSharedMemorySize,
                         SMEM_K4);

    gemm_h_w<<<dim3(128,4),256>>>(h, W);
    gat_attn_proj<<<(Bc*Hh*Nn)/8,256>>>(a_src, a_dst);
    gat_alpha<<<Bc*256,256>>>(adj, alpha_buf);
    gat_gemm<<<dim3(16,16),256,SMEM_K4>>>(alpha_buf, out);
}

// round 10
// speedup vs baseline: 2.1899x; 1.0651x over previous
#include <cuda_runtime.h>
#include <cstdint>

constexpr int Bc=4, Nn=2048, Dd=256, Hh=4;
constexpr int TJ=32, NT=Nn/TJ;   // 64 k-tiles in gat_gemm

__device__ float g_Wh  [Bc*Nn*Dd];   // ~fp32-exact, [b][j][c]
__device__ float g_WhR [Bc*Nn*Dd];   // tf32-rounded copy (B operand)
__device__ float g_esrc[Bc*Hh*Nn];
__device__ float g_edst[Bc*Hh*Nn];
__device__ float g_alpha_s[Bc*Hh*Nn*Nn];  // fallback if out buffer lacks alpha

__device__ __forceinline__ float totf(float x){
    uint32_t u; asm("cvt.rna.tf32.f32 %0, %1;" : "=r"(u) : "f"(x));
    return __uint_as_float(u);
}
__device__ __forceinline__ void mma8(float* d, float4 a, float2 b){
    asm volatile("mma.sync.aligned.m16n8k8.row.col.f32.tf32.tf32.f32 "
        "{%0,%1,%2,%3}, {%4,%5,%6,%7}, {%8,%9}, {%0,%1,%2,%3};"
        : "+f"(d[0]), "+f"(d[1]), "+f"(d[2]), "+f"(d[3])
        : "r"(__float_as_uint(a.x)), "r"(__float_as_uint(a.y)),
          "r"(__float_as_uint(a.z)), "r"(__float_as_uint(a.w)),
          "r"(__float_as_uint(b.x)), "r"(__float_as_uint(b.y)));
}
__device__ __forceinline__ void cpasync16(void* smem_p, const void* gmem){
    unsigned s = (unsigned)__cvta_generic_to_shared(smem_p);
    asm volatile("cp.async.cg.shared.global [%0], [%1], 16;" :: "r"(s), "l"(gmem));
}
#define CP_COMMIT() asm volatile("cp.async.commit_group;")
// wait so that group t is complete; rem = #groups issued after t still allowed pending
__device__ __forceinline__ void cp_wait_tail(int rem){
    if(rem>=2)      asm volatile("cp.async.wait_group 2;");
    else if(rem==1) asm volatile("cp.async.wait_group 1;");
    else            asm volatile("cp.async.wait_group 0;");
}

// ---------------------------------------------------------------------------
// K1: Wh = h @ W via 3-term tf32 split HMMA (fp32-accurate result).
// Block 256 thr: M=128 x N=64 tile; K=256 in 8 tiles of 32; 4-stage cp.async.
// Writes g_Wh (exact-ish) and g_WhR (tf32-rounded).
// ---------------------------------------------------------------------------
constexpr int AST=36, BST=72;
constexpr int ABUF=128*AST, BBUF=32*BST;          // floats per stage
constexpr int STG = ABUF + BBUF;                  // 6912 floats = 27648 B
constexpr int SMEM_PIPE = 4*STG*4;                // 110592 B

__global__ __launch_bounds__(256,2)
void gemm_h_w(const float* __restrict__ A, const float* __restrict__ Bw){
    extern __shared__ float sm[];
    const int tid = threadIdx.x, lane = tid & 31;
    const int i0 = blockIdx.x * 128;    // 64 M-tiles over 8192 rows
    const int n0 = blockIdx.y * 64;     // 4 N-tiles
    const int NT_K = 8;

    const int mq = (tid>>5)&3, nq = tid>>7;

    float acc[2][4][4];
#pragma unroll
    for(int mf=0;mf<2;mf++)
#pragma unroll
        for(int nf=0;nf<4;nf++)
#pragma unroll
            for(int q=0;q<4;q++) acc[mf][nf][q]=0.f;

    const int a_row = tid>>3, a_ch = tid&7;
    const int b_j   = tid>>4, b_ch = tid&15;

    auto stage = [&](int t){
        const int j0 = t*TJ;
        float* Asm = sm + (t&3)*STG;
        float* Bsm = Asm + ABUF;
#pragma unroll
        for(int k=0;k<4;k++){
            int row = a_row + k*32;
            cpasync16(Asm + row*AST + a_ch*4,
                      A + (size_t)(i0+row)*256 + j0 + a_ch*4);
        }
#pragma unroll
        for(int k=0;k<2;k++){
            int j = b_j + k*16;
            cpasync16(Bsm + j*BST + b_ch*4,
                      Bw + (size_t)(j0+j)*256 + n0 + b_ch*4);
        }
        CP_COMMIT();
    };

    stage(0); stage(1); stage(2);

    for(int t=0;t<NT_K;t++){
        cp_wait_tail(NT_K-1-t);
        __syncthreads();
        if(t+3 < NT_K) stage(t+3);
        const float* As = sm + (t&3)*STG;
        const float* Bs = As + ABUF;
#pragma unroll
        for(int kb=0;kb<4;kb++){
            float4 avb[2], avs[2];
#pragma unroll
            for(int mf=0;mf<2;mf++){
                int r = mq*32 + mf*16 + (lane>>2);
                int c = kb*8 + (lane&3);
                float4 av = make_float4(As[r*AST + c],     As[(r+8)*AST + c],
                                        As[r*AST + c + 4], As[(r+8)*AST + c + 4]);
                avb[mf] = make_float4(totf(av.x), totf(av.y), totf(av.z), totf(av.w));
                avs[mf] = make_float4(av.x-avb[mf].x, av.y-avb[mf].y,
                                      av.z-avb[mf].z, av.w-avb[mf].w);
            }
#pragma unroll
            for(int nf=0;nf<4;nf++){
                int bj = (kb*8 + (lane&3))*BST + nq*32 + nf*8 + (lane>>2);
                float2 bv = make_float2(Bs[bj], Bs[bj + 4*BST]);
                float2 bvb = make_float2(totf(bv.x), totf(bv.y));
                float2 bvs = make_float2(bv.x-bvb.x, bv.y-bvb.y);
#pragma unroll
                for(int mf=0;mf<2;mf++){
                    mma8(acc[mf][nf], avb[mf], bvb);
                    mma8(acc[mf][nf], avb[mf], bvs);
                    mma8(acc[mf][nf], avs[mf], bvb);
                }
            }
        }
    }

    const int r0 = i0 + mq*32, c0 = n0 + nq*32;
#pragma unroll
    for(int mf=0;mf<2;mf++){
        int row = r0 + mf*16 + (lane>>2);
        size_t o0 = (size_t)row*256 + c0 + (lane&3)*2;
        size_t o1 = o0 + (size_t)8*256;
#pragma unroll
        for(int nf=0;nf<4;nf++){
            float2 v0 = make_float2(acc[mf][nf][0], acc[mf][nf][1]);
            float2 v1 = make_float2(acc[mf][nf][2], acc[mf][nf][3]);
            *(float2*)(g_Wh + o0 + nf*8) = v0;
            *(float2*)(g_Wh + o1 + nf*8) = v1;
            *(float2*)(g_WhR + o0 + nf*8) = make_float2(totf(v0.x), totf(v0.y));
            *(float2*)(g_WhR + o1 + nf*8) = make_float2(totf(v1.x), totf(v1.y));
        }
    }
}

// ---------------------------------------------------------------------------
// K2: e_src/e_dst projections. One warp per (b,h,n).
// ---------------------------------------------------------------------------
__global__ __launch_bounds__(256)
void gat_attn_proj(const float* __restrict__ a_src, const float* __restrict__ a_dst){
    int r = blockIdx.x*8 + (threadIdx.x>>5);
    int lane = threadIdx.x & 31;
    int b = r>>13, h = (r>>11)&3, n = r & (Nn-1);
    const float* wp = g_Wh + ((size_t)(b*Nn+n))*Dd + h*64;
    float2 w  = *(const float2*)(wp + 2*lane);
    float2 as = *(const float2*)(a_src + h*64 + 2*lane);
    float2 ad = *(const float2*)(a_dst + h*64 + 2*lane);
    float ss = w.x*as.x + w.y*as.y;
    float sd = w.x*ad.x + w.y*ad.y;
#pragma unroll
    for(int o=16;o;o>>=1){
        ss += __shfl_xor_sync(0xffffffffu, ss, o);
        sd += __shfl_xor_sync(0xffffffffu, sd, o);
    }
    if(lane==0){ g_esrc[r]=ss; g_edst[r]=sd; }
}

// ---------------------------------------------------------------------------
// K3: alpha kernel. Block = (b, 8 rows), grid 1024, 256 thr. (near roofline)
// ---------------------------------------------------------------------------
__global__ __launch_bounds__(256)
void gat_alpha(const int* __restrict__ adj, float* __restrict__ alpha_out){
    __shared__ uint8_t bits[8*512];
    __shared__ float es[32], iv[32];
    const int tid = threadIdx.x;
    const int b  = blockIdx.x >> 8;
    const int i0 = (blockIdx.x & 255) * 8;

    if(tid<32) es[tid] = g_esrc[(b*Hh + (tid>>3))*Nn + i0 + (tid&7)];
    __syncthreads();

    {
        const int i = tid>>5, g = tid&31;
        const int*   arow = adj + ((size_t)(b*Nn + i0 + i))*Nn + g*4;
        const float* edb  = g_edst + (size_t)(b*Hh)*Nn + g*4;
        float E[4] = {es[i], es[8+i], es[16+i], es[24+i]};
        float S[4] = {0.f,0.f,0.f,0.f};
#pragma unroll 4
        for(int q=0;q<16;q++){
            int4 a = *(const int4*)(arow + q*128);
            float4 dv[4];
#pragma unroll
            for(int h=0;h<4;h++)
                dv[h] = *(const float4*)(edb + (size_t)h*Nn + q*128);
            int m[4] = {a.x, a.y, a.z, a.w};
#pragma unroll
            for(int jj=0;jj<4;jj++){
                bool mm = m[jj]!=0;
#pragma unroll
                for(int h=0;h<4;h++){
                    float e = E[h] + ((const float*)&dv[h])[jj];
                    e = (e>0.f)?e:0.2f*e;
                    if(mm) S[h] += __expf(e);
                }
            }
            bits[i*512 + q*32 + g] =
                (uint8_t)((m[0]?1u:0u)|(m[1]?2u:0u)|(m[2]?4u:0u)|(m[3]?8u:0u));
        }
#pragma unroll
        for(int h=0;h<4;h++)
#pragma unroll
            for(int o=16;o;o>>=1)
                S[h] += __shfl_xor_sync(0xffffffffu, S[h], o);
        if(g==0)
#pragma unroll
            for(int h=0;h<4;h++)
                iv[h*8+i] = (S[h]>0.f) ? (1.f/S[h]) : 0.f;
    }
    __syncthreads();

    const int h = tid>>6, c = tid&63;
    const float* edp = g_edst + (size_t)(b*Hh+h)*Nn;
    float* ab = alpha_out + ((size_t)((b*Hh+h)*Nn) + i0)*Nn;
    const float* esh = es + h*8;
    const float* ivh = iv + h*8;
#pragma unroll
    for(int jc=0;jc<8;jc++){
        const int j = jc*256 + c*4;
        float4 ed = *(const float4*)(edp + j);
#pragma unroll
        for(int i=0;i<8;i++){
            float E = esh[i], V = ivh[i];
            uint32_t nib = bits[i*512 + (j>>2)];
            float4 o; float e;
            e=E+ed.x; e=(e>0.f)?e:0.2f*e; o.x = (nib&1u)?__expf(e)*V:0.f;
            e=E+ed.y; e=(e>0.f)?e:0.2f*e; o.y = (nib&2u)?__expf(e)*V:0.f;
            e=E+ed.z; e=(e>0.f)?e:0.2f*e; o.z = (nib&4u)?__expf(e)*V:0.f;
            e=E+ed.w; e=(e>0.f)?e:0.2f*e; o.w = (nib&8u)?__expf(e)*V:0.f;
            *(float4*)(ab + (size_t)i*Nn + j) = o;
        }
    }
}

// ---------------------------------------------------------------------------
// K4: h_out = alpha @ WhR per (b,h). M=128, 4-stage cp.async, ONE barrier
// per tile, race-free tail waits.
// ---------------------------------------------------------------------------
__global__ __launch_bounds__(256,2)
void gat_gemm(const float* __restrict__ alpha, float* __restrict__ h_out){
    extern __shared__ float sm[];

    const int tid = threadIdx.x, lane = tid & 31;
    const int bh = blockIdx.y, b = bh>>2, h = bh&3;
    const int i0 = blockIdx.x * 128;
    const float* abase = alpha + ((size_t)bh*Nn + i0)*Nn;
    const float* wbase = g_WhR + (size_t)b*Nn*Dd + h*64;

    const int mq = (tid>>5)&3, nq = tid>>7;

    float acc[2][4][4];
#pragma unroll
    for(int mf=0;mf<2;mf++)
#pragma unroll
        for(int nf=0;nf<4;nf++)
#pragma unroll
            for(int q=0;q<4;q++) acc[mf][nf][q]=0.f;

    const int a_row = tid>>3, a_ch = tid&7;
    const int b_j   = tid>>4, b_ch = tid&15;

    auto stage = [&](int t){
        const int j0 = t*TJ;
        float* Asm = sm + (t&3)*STG;
        float* Bsm = Asm + ABUF;
#pragma unroll
        for(int k=0;k<4;k++){
            int row = a_row + k*32;
            cpasync16(Asm + row*AST + a_ch*4,
                      abase + (size_t)row*Nn + j0 + a_ch*4);
        }
#pragma unroll
        for(int k=0;k<2;k++){
            int j = b_j + k*16;
            cpasync16(Bsm + j*BST + b_ch*4,
                      wbase + (size_t)(j0+j)*Dd + b_ch*4);
        }
        CP_COMMIT();
    };

    stage(0); stage(1); stage(2);

    for(int t=0;t<NT;t++){
        cp_wait_tail(NT-1-t);
        __syncthreads();
        if(t+3 < NT) stage(t+3);
        const float* As = sm + (t&3)*STG;
        const float* Bs = As + ABUF;
#pragma unroll
        for(int kb=0;kb<4;kb++){
            float4 av[2];
#pragma unroll
            for(int mf=0;mf<2;mf++){
                int r = mq*32 + mf*16 + (lane>>2);
                int c = kb*8 + (lane&3);
                av[mf] = make_float4(As[r*AST + c],     As[(r+8)*AST + c],
                                     As[r*AST + c + 4], As[(r+8)*AST + c + 4]);
            }
            float2 bv[4];
#pragma unroll
            for(int nf=0;nf<4;nf++){
                int bj = (kb*8 + (lane&3))*BST + nq*32 + nf*8 + (lane>>2);
                bv[nf] = make_float2(Bs[bj], Bs[bj + 4*BST]);
            }
#pragma unroll
            for(int mf=0;mf<2;mf++)
#pragma unroll
                for(int nf=0;nf<4;nf++)
                    mma8(acc[mf][nf], av[mf], bv[nf]);
        }
    }

    const int r0 = i0 + mq*32, c0 = h*64 + nq*32;
#pragma unroll
    for(int mf=0;mf<2;mf++){
        int row = r0 + mf*16 + (lane>>2);
        float* p0 = h_out + ((size_t)(b*Nn) + row)*Dd + c0 + (lane&3)*2;
        float* p1 = p0 + (size_t)8*Dd;
#pragma unroll
        for(int nf=0;nf<4;nf++){
            *(float2*)(p0 + nf*8) = make_float2(acc[mf][nf][0], acc[mf][nf][1]);
            *(float2*)(p1 + nf*8) = make_float2(acc[mf][nf][2], acc[mf][nf][3]);
        }
    }
}

// ---------------------------------------------------------------------------
extern "C" void kernel_launch(void* const* d_in, const int* in_sizes, int n_in,
                              void* d_out, int out_size){
    const float* h     = (const float*)d_in[0];
    const int*   adj   = (const int*)d_in[1];
    const float* W     = (const float*)d_in[2];
    const float* a_src = (const float*)d_in[3];
    const float* a_dst = (const float*)d_in[4];
    float* out = (float*)d_out;

    const long long houtN  = (long long)Bc*Nn*Dd;
    const long long alphaN = (long long)Bc*Hh*Nn*Nn;
    bool has_alpha = ((long long)out_size >= houtN + alphaN);
    float* alpha_buf;
    if(has_alpha){
        alpha_buf = out + houtN;
    } else {
        cudaGetSymbolAddress((void**)&alpha_buf, g_alpha_s);
    }

    cudaFuncSetAttribute(gemm_h_w, cudaFuncAttributeMaxDynamicSharedMemorySize,
                         SMEM_PIPE);
    cudaFuncSetAttribute(gat_gemm, cudaFuncAttributeMaxDynamicSharedMemorySize,
                         SMEM_PIPE);

    gemm_h_w<<<dim3(64,4),256,SMEM_PIPE>>>(h, W);
    gat_attn_proj<<<(Bc*Hh*Nn)/8,256>>>(a_src, a_dst);
    gat_alpha<<<Bc*256,256>>>(adj, alpha_buf);
    gat_gemm<<<dim3(16,16),256,SMEM_PIPE>>>(alpha_buf, out);
}